// round 16
// baseline (speedup 1.0000x reference)
#include <cuda_runtime.h>
#include <cuda_bf16.h>
#include <cstdint>

// Problem constants (GCN2: N=50000 nodes, E=800000 edges, 128 -> 128 -> 64)
#define NMAX 50000
#define EMAX 800000
#define DIN  128
#define DHID 128
#define DOUT 64
#define NBLK ((NMAX + 255) / 256)

// ---------------- scratch (device globals; no allocations allowed) ----------
__device__ int   g_deg[NMAX];
__device__ int   g_rowptr[NMAX + 1];
__device__ int   g_cursor[NMAX];
__device__ __align__(16) int2  g_csr[EMAX];
__device__ float g_dinv[NMAX];
__device__ __align__(16) float g_h1[NMAX * DHID];
__device__ __align__(16) float g_h2[NMAX * DOUT];
// decoupled-lookback scan state
__device__ int                g_ticket;
__device__ unsigned long long g_blk_state[NBLK];   // (flag<<32)|value; flag 1=agg, 2=prefix
// bf16 hi/lo split operands for tensor GEMMs
__device__ __align__(16) __nv_bfloat16 g_a1hi[NMAX * DHID];
__device__ __align__(16) __nv_bfloat16 g_a1lo[NMAX * DHID];
__device__ __align__(16) __nv_bfloat16 g_w1thi[DHID * DIN];   // [n][k]
__device__ __align__(16) __nv_bfloat16 g_w1tlo[DHID * DIN];
__device__ __align__(16) __nv_bfloat16 g_w2thi[DOUT * DHID];  // [n][k]
__device__ __align__(16) __nv_bfloat16 g_w2tlo[DOUT * DHID];

// ---------------- bf16 hi/lo split helpers -----------------------------------
__device__ __forceinline__ uint32_t pack2(float a, float b, float* ra, float* rb) {
    __nv_bfloat16 ha = __float2bfloat16(a), hb = __float2bfloat16(b);
    *ra = a - __bfloat162float(ha);
    *rb = b - __bfloat162float(hb);
    return (uint32_t)__bfloat16_as_ushort(ha) | ((uint32_t)__bfloat16_as_ushort(hb) << 16);
}
__device__ __forceinline__ uint32_t pack2b(float a, float b) {
    __nv_bfloat16 ha = __float2bfloat16(a), hb = __float2bfloat16(b);
    return (uint32_t)__bfloat16_as_ushort(ha) | ((uint32_t)__bfloat16_as_ushort(hb) << 16);
}

// ---------------- per-warp edge dtype detection -------------------------------
__device__ __forceinline__ int warp_is64(const int* __restrict__ ei32) {
    int lane = threadIdx.x & 31;
    int v = (lane < 16) ? ei32[2 * lane + 1] : 0;
    unsigned nz = __ballot_sync(0xFFFFFFFF, v != 0);
    return nz == 0;
}

// ---------------- fused: degree count + W split + scan-state reset ------------
__global__ void count_w_kernel(const void* __restrict__ ei, int E, int n, int eblocks,
                               const float* __restrict__ W1, const float* __restrict__ W2) {
    if (blockIdx.x < (unsigned)eblocks) {
        int is64 = warp_is64((const int*)ei);
        int e = blockIdx.x * 256 + threadIdx.x;
        if (e < E) {
            long long idx = (long long)E + e;
            int dst = is64 ? (int)((const long long*)ei)[idx] : ((const int*)ei)[idx];
            if ((unsigned)dst < (unsigned)n) atomicAdd(&g_deg[dst], 1);
        }
    } else {
        int idx = (blockIdx.x - eblocks) * 256 + threadIdx.x;
        if (idx < DIN * DHID) {
            int k = idx >> 7, n_ = idx & 127;       // W1[k][n]
            float v = W1[idx];
            __nv_bfloat16 h = __float2bfloat16(v);
            g_w1thi[n_ * 128 + k] = h;
            g_w1tlo[n_ * 128 + k] = __float2bfloat16(v - __bfloat162float(h));
        }
        if (idx < DHID * DOUT) {
            int k = idx >> 6, n_ = idx & 63;        // W2[k][n]
            float v = W2[idx];
            __nv_bfloat16 h = __float2bfloat16(v);
            g_w2thi[n_ * 128 + k] = h;
            g_w2tlo[n_ * 128 + k] = __float2bfloat16(v - __bfloat162float(h));
        }
        // reset lookback-scan state for this call (ordered before scan kernel)
        if (idx < NBLK) g_blk_state[idx] = 0ULL;
        if (idx == 0)   g_ticket = 0;
    }
}

// ---------------- single-kernel decoupled-lookback scan -----------------------
// Replaces scan1/scan2/scan3: produces rowptr, cursor, dinv in one launch.
__global__ __launch_bounds__(256) void scan_fused_kernel(int n, int nb) {
    __shared__ int s[256];
    __shared__ int s_bid;
    __shared__ int s_excl;
    int t = threadIdx.x;
    if (t == 0) s_bid = atomicAdd(&g_ticket, 1);   // scheduling-ordered block id
    __syncthreads();
    int b = s_bid;
    int i = b * 256 + t;
    int d = (i < n) ? g_deg[i] : 0;
    s[t] = d;
    __syncthreads();
#pragma unroll
    for (int off = 1; off < 256; off <<= 1) {
        int v = (t >= off) ? s[t - off] : 0;
        __syncthreads();
        s[t] += v;
        __syncthreads();
    }
    int total = s[255];

    if (t == 0) {
        if (b == 0) {
            __threadfence();
            atomicExch(&g_blk_state[0], (2ULL << 32) | (unsigned)total);
            s_excl = 0;
        } else {
            // publish aggregate
            __threadfence();
            atomicExch(&g_blk_state[b], (1ULL << 32) | (unsigned)total);
            // lookback
            int run = 0;
            int pb = b - 1;
            while (true) {
                unsigned long long st;
                do { st = atomicAdd(&g_blk_state[pb], 0ULL); } while ((st >> 32) == 0);
                run += (int)(unsigned)st;
                if ((st >> 32) == 2) break;
                pb--;
            }
            s_excl = run;
            __threadfence();
            atomicExch(&g_blk_state[b], (2ULL << 32) | (unsigned)(run + total));
        }
    }
    __syncthreads();
    int excl = s_excl;
    if (i < n) {
        int r = excl + s[t] - d;
        g_rowptr[i] = r;
        g_cursor[i] = r;
        g_dinv[i]   = rsqrtf((float)d + 1.0f);
    }
    if (b == nb - 1 && t == 255) g_rowptr[n] = excl + total;
}

__global__ void fill_csr_kernel(const void* __restrict__ ei, int E, int n) {
    int is64 = warp_is64((const int*)ei);
    int e = blockIdx.x * blockDim.x + threadIdx.x;
    if (e < E) {
        int src, dst;
        if (is64) {
            src = (int)((const long long*)ei)[e];
            dst = (int)((const long long*)ei)[(long long)E + e];
        } else {
            src = ((const int*)ei)[e];
            dst = ((const int*)ei)[(long long)E + e];
        }
        if ((unsigned)src < (unsigned)n && (unsigned)dst < (unsigned)n) {
            int pos = atomicAdd(&g_cursor[dst], 1);
            g_csr[pos] = make_int2(src, __float_as_int(g_dinv[src]));
        }
    }
}

// ---------------- mma.sync bf16 GEMM (identical to round 15) ------------------
__device__ __forceinline__ void mma16816(float* c, const uint32_t* a,
                                         uint32_t b0, uint32_t b1) {
    asm volatile(
        "mma.sync.aligned.m16n8k16.row.col.f32.bf16.bf16.f32 "
        "{%0,%1,%2,%3}, {%4,%5,%6,%7}, {%8,%9}, {%0,%1,%2,%3};"
        : "+f"(c[0]), "+f"(c[1]), "+f"(c[2]), "+f"(c[3])
        : "r"(a[0]), "r"(a[1]), "r"(a[2]), "r"(a[3]), "r"(b0), "r"(b1));
}

template <int NCOLS, bool AF32>
__global__ __launch_bounds__(256) void tgemm_kernel(
    const void* __restrict__ Aa, const void* __restrict__ Ab,
    const __nv_bfloat16* __restrict__ Bhi_g, const __nv_bfloat16* __restrict__ Blo_g,
    float* __restrict__ H, int n)
{
    constexpr int KS = 40;
    constexpr int NAT = NCOLS / 16;
    __shared__ __align__(16) __nv_bfloat16 sAh[128 * KS];
    __shared__ __align__(16) __nv_bfloat16 sAl[128 * KS];
    __shared__ __align__(16) __nv_bfloat16 sBh[NCOLS * KS];
    __shared__ __align__(16) __nv_bfloat16 sBl[NCOLS * KS];

    const int tid = threadIdx.x;
    const int wid = tid >> 5, lane = tid & 31;
    const int g = lane >> 2, tg = lane & 3;
    const int wr = wid & 3;
    const int wc = wid >> 2;
    const int r0 = blockIdx.x * 128;

    float acc[2][NAT][4];
#pragma unroll
    for (int mi = 0; mi < 2; mi++)
#pragma unroll
        for (int ni = 0; ni < NAT; ni++)
#pragma unroll
            for (int q = 0; q < 4; q++) acc[mi][ni][q] = 0.0f;

    for (int s = 0; s < 4; s++) {
        for (int i = tid; i < 512; i += 256) {
            int row = i >> 2, ch = i & 3;
            int gr = r0 + row;
            uint4 vh = make_uint4(0, 0, 0, 0), vl = vh;
            if (AF32) {
                if (gr < n) {
                    const float4* X4 = (const float4*)Aa;
                    float4 f0 = X4[gr * 32 + (s * 4 + ch) * 2];
                    float4 f1 = X4[gr * 32 + (s * 4 + ch) * 2 + 1];
                    float rr[8];
                    vh.x = pack2(f0.x, f0.y, &rr[0], &rr[1]);
                    vh.y = pack2(f0.z, f0.w, &rr[2], &rr[3]);
                    vh.z = pack2(f1.x, f1.y, &rr[4], &rr[5]);
                    vh.w = pack2(f1.z, f1.w, &rr[6], &rr[7]);
                    vl.x = pack2b(rr[0], rr[1]); vl.y = pack2b(rr[2], rr[3]);
                    vl.z = pack2b(rr[4], rr[5]); vl.w = pack2b(rr[6], rr[7]);
                }
            } else {
                if (gr < n) {
                    vh = ((const uint4*)Aa)[gr * 16 + s * 4 + ch];
                    vl = ((const uint4*)Ab)[gr * 16 + s * 4 + ch];
                }
            }
            *(uint4*)&sAh[row * KS + ch * 8] = vh;
            *(uint4*)&sAl[row * KS + ch * 8] = vl;
        }
        for (int i = tid; i < NCOLS * 4; i += 256) {
            int row = i >> 2, ch = i & 3;
            *(uint4*)&sBh[row * KS + ch * 8] = ((const uint4*)Bhi_g)[row * 16 + s * 4 + ch];
            *(uint4*)&sBl[row * KS + ch * 8] = ((const uint4*)Blo_g)[row * 16 + s * 4 + ch];
        }
        __syncthreads();

#pragma unroll
        for (int pass = 0; pass < 3; pass++) {
            const __nv_bfloat16* sA = (pass == 2) ? sAl : sAh;
            const __nv_bfloat16* sB = (pass == 1) ? sBl : sBh;
#pragma unroll
            for (int kk = 0; kk < 2; kk++) {
                uint32_t a[2][4];
#pragma unroll
                for (int mi = 0; mi < 2; mi++) {
                    int rb = (wr * 32 + mi * 16 + g) * KS + kk * 16 + tg * 2;
                    a[mi][0] = *(const uint32_t*)&sA[rb];
                    a[mi][1] = *(const uint32_t*)&sA[rb + 8 * KS];
                    a[mi][2] = *(const uint32_t*)&sA[rb + 8];
                    a[mi][3] = *(const uint32_t*)&sA[rb + 8 * KS + 8];
                }
#pragma unroll
                for (int ni = 0; ni < NAT; ni++) {
                    int nb = (wc * (NCOLS / 2) + ni * 8 + g) * KS + kk * 16 + tg * 2;
                    uint32_t b0 = *(const uint32_t*)&sB[nb];
                    uint32_t b1 = *(const uint32_t*)&sB[nb + 8];
                    mma16816(acc[0][ni], a[0], b0, b1);
                    mma16816(acc[1][ni], a[1], b0, b1);
                }
            }
        }
        __syncthreads();
    }

#pragma unroll
    for (int mi = 0; mi < 2; mi++) {
        int r = r0 + wr * 32 + mi * 16 + g;
#pragma unroll
        for (int ni = 0; ni < NAT; ni++) {
            int c = wc * (NCOLS / 2) + ni * 8 + tg * 2;
            if (r < n)
                *(float2*)&H[(long long)r * NCOLS + c] = make_float2(acc[mi][ni][0], acc[mi][ni][1]);
            if (r + 8 < n)
                *(float2*)&H[(long long)(r + 8) * NCOLS + c] = make_float2(acc[mi][ni][2], acc[mi][ni][3]);
        }
    }
}

// ---------------- CSR aggregation (identical to round 15) ---------------------
__global__ __launch_bounds__(256) void agg128_kernel(const float* __restrict__ H,
                                                     const float* __restrict__ bias,
                                                     __nv_bfloat16* __restrict__ a1hi,
                                                     __nv_bfloat16* __restrict__ a1lo,
                                                     int n) {
    int warp = (blockIdx.x * blockDim.x + threadIdx.x) >> 5;
    int lane = threadIdx.x & 31;
    if (warp >= n) return;

    float4 acc0 = make_float4(0.f, 0.f, 0.f, 0.f);
    float4 acc1 = make_float4(0.f, 0.f, 0.f, 0.f);
    float4 acc2 = make_float4(0.f, 0.f, 0.f, 0.f);
    float4 acc3 = make_float4(0.f, 0.f, 0.f, 0.f);
    int beg = g_rowptr[warp], end = g_rowptr[warp + 1];
    const float4* H4 = (const float4*)H;
    int p = beg;
    for (; p + 7 < end; p += 8) {
        int2 e0 = g_csr[p];     int2 e1 = g_csr[p + 1];
        int2 e2 = g_csr[p + 2]; int2 e3 = g_csr[p + 3];
        int2 e4 = g_csr[p + 4]; int2 e5 = g_csr[p + 5];
        int2 e6 = g_csr[p + 6]; int2 e7 = g_csr[p + 7];
        float4 v0 = H4[e0.x * 32 + lane]; float4 v1 = H4[e1.x * 32 + lane];
        float4 v2 = H4[e2.x * 32 + lane]; float4 v3 = H4[e3.x * 32 + lane];
        float4 v4 = H4[e4.x * 32 + lane]; float4 v5 = H4[e5.x * 32 + lane];
        float4 v6 = H4[e6.x * 32 + lane]; float4 v7 = H4[e7.x * 32 + lane];
        float w0 = __int_as_float(e0.y), w1 = __int_as_float(e1.y);
        float w2 = __int_as_float(e2.y), w3 = __int_as_float(e3.y);
        float w4 = __int_as_float(e4.y), w5 = __int_as_float(e5.y);
        float w6 = __int_as_float(e6.y), w7 = __int_as_float(e7.y);
        acc0.x += w0 * v0.x; acc0.y += w0 * v0.y; acc0.z += w0 * v0.z; acc0.w += w0 * v0.w;
        acc1.x += w1 * v1.x; acc1.y += w1 * v1.y; acc1.z += w1 * v1.z; acc1.w += w1 * v1.w;
        acc2.x += w2 * v2.x; acc2.y += w2 * v2.y; acc2.z += w2 * v2.z; acc2.w += w2 * v2.w;
        acc3.x += w3 * v3.x; acc3.y += w3 * v3.y; acc3.z += w3 * v3.z; acc3.w += w3 * v3.w;
        acc0.x += w4 * v4.x; acc0.y += w4 * v4.y; acc0.z += w4 * v4.z; acc0.w += w4 * v4.w;
        acc1.x += w5 * v5.x; acc1.y += w5 * v5.y; acc1.z += w5 * v5.z; acc1.w += w5 * v5.w;
        acc2.x += w6 * v6.x; acc2.y += w6 * v6.y; acc2.z += w6 * v6.z; acc2.w += w6 * v6.w;
        acc3.x += w7 * v7.x; acc3.y += w7 * v7.y; acc3.z += w7 * v7.z; acc3.w += w7 * v7.w;
    }
    for (; p < end; p++) {
        int2 e0 = g_csr[p];
        float4 v0 = H4[e0.x * 32 + lane];
        float w0 = __int_as_float(e0.y);
        acc0.x += w0 * v0.x; acc0.y += w0 * v0.y; acc0.z += w0 * v0.z; acc0.w += w0 * v0.w;
    }
    acc0.x += acc1.x + acc2.x + acc3.x;
    acc0.y += acc1.y + acc2.y + acc3.y;
    acc0.z += acc1.z + acc2.z + acc3.z;
    acc0.w += acc1.w + acc2.w + acc3.w;

    float di = g_dinv[warp];
    float d2 = di * di;
    float4 hv = H4[warp * 32 + lane];
    float4 bv = ((const float4*)bias)[lane];
    float4 o;
    o.x = fmaxf(di * acc0.x + d2 * hv.x + bv.x, 0.f);
    o.y = fmaxf(di * acc0.y + d2 * hv.y + bv.y, 0.f);
    o.z = fmaxf(di * acc0.z + d2 * hv.z + bv.z, 0.f);
    o.w = fmaxf(di * acc0.w + d2 * hv.w + bv.w, 0.f);

    float rx, ry, rz, rw;
    uint2 hi, lo;
    hi.x = pack2(o.x, o.y, &rx, &ry);
    hi.y = pack2(o.z, o.w, &rz, &rw);
    lo.x = pack2b(rx, ry);
    lo.y = pack2b(rz, rw);
    ((uint2*)a1hi)[warp * 32 + lane] = hi;
    ((uint2*)a1lo)[warp * 32 + lane] = lo;
}

__global__ __launch_bounds__(256) void agg64_kernel(const float* __restrict__ H,
                                                    const float* __restrict__ bias,
                                                    float* __restrict__ out, int n) {
    int warp = (blockIdx.x * blockDim.x + threadIdx.x) >> 5;
    int lane = threadIdx.x & 31;
    if (warp >= n) return;

    float2 acc0 = make_float2(0.f, 0.f);
    float2 acc1 = make_float2(0.f, 0.f);
    float2 acc2 = make_float2(0.f, 0.f);
    float2 acc3 = make_float2(0.f, 0.f);
    int beg = g_rowptr[warp], end = g_rowptr[warp + 1];
    const float2* H2 = (const float2*)H;
    int p = beg;
    for (; p + 7 < end; p += 8) {
        int2 e0 = g_csr[p];     int2 e1 = g_csr[p + 1];
        int2 e2 = g_csr[p + 2]; int2 e3 = g_csr[p + 3];
        int2 e4 = g_csr[p + 4]; int2 e5 = g_csr[p + 5];
        int2 e6 = g_csr[p + 6]; int2 e7 = g_csr[p + 7];
        float2 v0 = H2[e0.x * 32 + lane]; float2 v1 = H2[e1.x * 32 + lane];
        float2 v2 = H2[e2.x * 32 + lane]; float2 v3 = H2[e3.x * 32 + lane];
        float2 v4 = H2[e4.x * 32 + lane]; float2 v5 = H2[e5.x * 32 + lane];
        float2 v6 = H2[e6.x * 32 + lane]; float2 v7 = H2[e7.x * 32 + lane];
        float w0 = __int_as_float(e0.y), w1 = __int_as_float(e1.y);
        float w2 = __int_as_float(e2.y), w3 = __int_as_float(e3.y);
        float w4 = __int_as_float(e4.y), w5 = __int_as_float(e5.y);
        float w6 = __int_as_float(e6.y), w7 = __int_as_float(e7.y);
        acc0.x += w0 * v0.x; acc0.y += w0 * v0.y;
        acc1.x += w1 * v1.x; acc1.y += w1 * v1.y;
        acc2.x += w2 * v2.x; acc2.y += w2 * v2.y;
        acc3.x += w3 * v3.x; acc3.y += w3 * v3.y;
        acc0.x += w4 * v4.x; acc0.y += w4 * v4.y;
        acc1.x += w5 * v5.x; acc1.y += w5 * v5.y;
        acc2.x += w6 * v6.x; acc2.y += w6 * v6.y;
        acc3.x += w7 * v7.x; acc3.y += w7 * v7.y;
    }
    for (; p < end; p++) {
        int2 e0 = g_csr[p];
        float2 v0 = H2[e0.x * 32 + lane];
        float w0 = __int_as_float(e0.y);
        acc0.x += w0 * v0.x; acc0.y += w0 * v0.y;
    }
    acc0.x += acc1.x + acc2.x + acc3.x;
    acc0.y += acc1.y + acc2.y + acc3.y;

    float di = g_dinv[warp];
    float d2 = di * di;
    float2 hv = H2[warp * 32 + lane];
    float2 bv = ((const float2*)bias)[lane];
    float2 o;
    o.x = di * acc0.x + d2 * hv.x + bv.x;
    o.y = di * acc0.y + d2 * hv.y + bv.y;
    ((float2*)out)[warp * 32 + lane] = o;
}

// ---------------- launch ------------------------------------------------------
extern "C" void kernel_launch(void* const* d_in, const int* in_sizes, int n_in,
                              void* d_out, int out_size) {
    const float* x   = (const float*)d_in[0];
    const void*  ei  = d_in[1];
    const float* W1  = (const float*)d_in[2];
    const float* b1  = (const float*)d_in[3];
    const float* W2  = (const float*)d_in[4];
    const float* b2  = (const float*)d_in[5];
    float*       out = (float*)d_out;

    const int N  = in_sizes[0] / DIN;   // 50000
    const int E  = in_sizes[1] / 2;     // 800000
    const int nb = (N + 255) / 256;     // 196
    const int eblocks = (E + 255) / 256;
    const int wblocks = (DIN * DHID + 255) / 256;  // 64

    void *p_h1, *p_h2, *p_deg, *p_a1hi, *p_a1lo;
    void *p_w1h, *p_w1l, *p_w2h, *p_w2l;
    cudaGetSymbolAddress(&p_h1, g_h1);
    cudaGetSymbolAddress(&p_h2, g_h2);
    cudaGetSymbolAddress(&p_deg, g_deg);
    cudaGetSymbolAddress(&p_a1hi, g_a1hi);
    cudaGetSymbolAddress(&p_a1lo, g_a1lo);
    cudaGetSymbolAddress(&p_w1h, g_w1thi);
    cudaGetSymbolAddress(&p_w1l, g_w1tlo);
    cudaGetSymbolAddress(&p_w2h, g_w2thi);
    cudaGetSymbolAddress(&p_w2l, g_w2tlo);

    // graph build: memset + count/W-split/scan-reset + lookback scan + fill
    cudaMemsetAsync(p_deg, 0, N * sizeof(int));
    count_w_kernel<<<eblocks + wblocks, 256>>>(ei, E, N, eblocks, W1, W2);
    scan_fused_kernel<<<nb, 256>>>(N, nb);
    fill_csr_kernel<<<eblocks, 256>>>(ei, E, N);

    const int gtiles = (N + 127) / 128;

    // layer 1: h1 = x @ W1 (mma.sync, fused fp32->hi/lo split) ; a1 = relu(conv1)
    tgemm_kernel<DHID, true><<<gtiles, 256>>>(
        x, nullptr,
        (const __nv_bfloat16*)p_w1h, (const __nv_bfloat16*)p_w1l,
        (float*)p_h1, N);
    agg128_kernel<<<(N + 7) / 8, 256>>>((const float*)p_h1, b1,
                                        (__nv_bfloat16*)p_a1hi, (__nv_bfloat16*)p_a1lo, N);

    // layer 2: h2 = a1 @ W2 (mma.sync) ; out = conv2
    tgemm_kernel<DOUT, false><<<gtiles, 256>>>(
        p_a1hi, p_a1lo,
        (const __nv_bfloat16*)p_w2h, (const __nv_bfloat16*)p_w2l,
        (float*)p_h2, N);
    agg64_kernel<<<(N + 7) / 8, 256>>>((const float*)p_h2, b2, out, N);
}

// round 17
// speedup vs baseline: 1.0912x; 1.0912x over previous
#include <cuda_runtime.h>
#include <cuda_bf16.h>
#include <cstdint>

// Problem constants (GCN2: N=50000 nodes, E=800000 edges, 128 -> 128 -> 64)
#define NMAX 50000
#define EMAX 800000
#define DIN  128
#define DHID 128
#define DOUT 64
#define NBLK ((NMAX + 255) / 256)

// ---------------- scratch (device globals; no allocations allowed) ----------
__device__ int   g_deg[NMAX];
__device__ int   g_locexc[NMAX];
__device__ int   g_part[NBLK];
__device__ int   g_rowptr[NMAX + 1];
__device__ int   g_cursor[NMAX];
__device__ __align__(16) int2  g_csr[EMAX];
__device__ float g_dinv[NMAX];
__device__ __align__(16) float g_h1[NMAX * DHID];
__device__ __align__(16) float g_h2[NMAX * DOUT];
// bf16 hi/lo split operands for tensor GEMMs
__device__ __align__(16) __nv_bfloat16 g_a1hi[NMAX * DHID];
__device__ __align__(16) __nv_bfloat16 g_a1lo[NMAX * DHID];
__device__ __align__(16) __nv_bfloat16 g_w1thi[DHID * DIN];   // [n][k]
__device__ __align__(16) __nv_bfloat16 g_w1tlo[DHID * DIN];
__device__ __align__(16) __nv_bfloat16 g_w2thi[DOUT * DHID];  // [n][k]
__device__ __align__(16) __nv_bfloat16 g_w2tlo[DOUT * DHID];

// ---------------- bf16 hi/lo split helpers -----------------------------------
__device__ __forceinline__ uint32_t pack2(float a, float b, float* ra, float* rb) {
    __nv_bfloat16 ha = __float2bfloat16(a), hb = __float2bfloat16(b);
    *ra = a - __bfloat162float(ha);
    *rb = b - __bfloat162float(hb);
    return (uint32_t)__bfloat16_as_ushort(ha) | ((uint32_t)__bfloat16_as_ushort(hb) << 16);
}
__device__ __forceinline__ uint32_t pack2b(float a, float b) {
    __nv_bfloat16 ha = __float2bfloat16(a), hb = __float2bfloat16(b);
    return (uint32_t)__bfloat16_as_ushort(ha) | ((uint32_t)__bfloat16_as_ushort(hb) << 16);
}

// ---------------- per-warp edge dtype detection -------------------------------
__device__ __forceinline__ int warp_is64(const int* __restrict__ ei32) {
    int lane = threadIdx.x & 31;
    int v = (lane < 16) ? ei32[2 * lane + 1] : 0;
    unsigned nz = __ballot_sync(0xFFFFFFFF, v != 0);
    return nz == 0;
}

// ---------------- fused: degree count (edge blocks) + W split (tail blocks) ---
__global__ void count_w_kernel(const void* __restrict__ ei, int E, int n, int eblocks,
                               const float* __restrict__ W1, const float* __restrict__ W2) {
    if (blockIdx.x < (unsigned)eblocks) {
        int is64 = warp_is64((const int*)ei);
        int e = blockIdx.x * 256 + threadIdx.x;
        if (e < E) {
            long long idx = (long long)E + e;
            int dst = is64 ? (int)((const long long*)ei)[idx] : ((const int*)ei)[idx];
            if ((unsigned)dst < (unsigned)n) atomicAdd(&g_deg[dst], 1);
        }
    } else {
        int idx = (blockIdx.x - eblocks) * 256 + threadIdx.x;
        if (idx < DIN * DHID) {
            int k = idx >> 7, n_ = idx & 127;       // W1[k][n]
            float v = W1[idx];
            __nv_bfloat16 h = __float2bfloat16(v);
            g_w1thi[n_ * 128 + k] = h;
            g_w1tlo[n_ * 128 + k] = __float2bfloat16(v - __bfloat162float(h));
        }
        if (idx < DHID * DOUT) {
            int k = idx >> 6, n_ = idx & 63;        // W2[k][n]
            float v = W2[idx];
            __nv_bfloat16 h = __float2bfloat16(v);
            g_w2thi[n_ * 128 + k] = h;
            g_w2tlo[n_ * 128 + k] = __float2bfloat16(v - __bfloat162float(h));
        }
    }
}

// ---------------- 3-phase parallel scan (round-15 proven version) -------------
__global__ __launch_bounds__(256) void scan1_kernel(int n) {
    __shared__ int s[256];
    int t = threadIdx.x;
    int i = blockIdx.x * 256 + t;
    int d = (i < n) ? g_deg[i] : 0;
    s[t] = d;
    __syncthreads();
#pragma unroll
    for (int off = 1; off < 256; off <<= 1) {
        int v = (t >= off) ? s[t - off] : 0;
        __syncthreads();
        s[t] += v;
        __syncthreads();
    }
    if (i < n) {
        g_locexc[i] = s[t] - d;
        g_dinv[i]   = rsqrtf((float)d + 1.0f);
    }
    if (t == 255) g_part[blockIdx.x] = s[255];
}
__global__ __launch_bounds__(256) void scan2_kernel(int nb) {
    __shared__ int s[256];
    int t = threadIdx.x;
    s[t] = (t < nb) ? g_part[t] : 0;
    __syncthreads();
#pragma unroll
    for (int off = 1; off < 256; off <<= 1) {
        int v = (t >= off) ? s[t - off] : 0;
        __syncthreads();
        s[t] += v;
        __syncthreads();
    }
    if (t < nb) g_part[t] = s[t];
}
__global__ __launch_bounds__(256) void scan3_kernel(int n, int nb) {
    int b = blockIdx.x;
    int i = b * 256 + threadIdx.x;
    int off = (b == 0) ? 0 : g_part[b - 1];
    if (i < n) {
        int r = off + g_locexc[i];
        g_rowptr[i] = r;
        g_cursor[i] = r;
    }
    if (i == 0) g_rowptr[n] = g_part[nb - 1];
}
__global__ void fill_csr_kernel(const void* __restrict__ ei, int E, int n) {
    int is64 = warp_is64((const int*)ei);
    int e = blockIdx.x * blockDim.x + threadIdx.x;
    if (e < E) {
        int src, dst;
        if (is64) {
            src = (int)((const long long*)ei)[e];
            dst = (int)((const long long*)ei)[(long long)E + e];
        } else {
            src = ((const int*)ei)[e];
            dst = ((const int*)ei)[(long long)E + e];
        }
        if ((unsigned)src < (unsigned)n && (unsigned)dst < (unsigned)n) {
            int pos = atomicAdd(&g_cursor[dst], 1);
            g_csr[pos] = make_int2(src, __float_as_int(g_dinv[src]));
        }
    }
}

// ---------------- mma.sync bf16 GEMM ------------------------------------------
// H[n, NCOLS] = A[n,128] @ Bt[NCOLS,128]^T, hi/lo split (3 passes), fp32 accum.
// __launch_bounds__(256, 2): cap regs at 128 -> 2 blocks/SM (was 134 regs,
// 1 block/SM, occ 12.4%, tensor pipe 18.8% -- latency-bound per R16 ncu).
__device__ __forceinline__ void mma16816(float* c, const uint32_t* a,
                                         uint32_t b0, uint32_t b1) {
    asm volatile(
        "mma.sync.aligned.m16n8k16.row.col.f32.bf16.bf16.f32 "
        "{%0,%1,%2,%3}, {%4,%5,%6,%7}, {%8,%9}, {%0,%1,%2,%3};"
        : "+f"(c[0]), "+f"(c[1]), "+f"(c[2]), "+f"(c[3])
        : "r"(a[0]), "r"(a[1]), "r"(a[2]), "r"(a[3]), "r"(b0), "r"(b1));
}

template <int NCOLS, bool AF32>
__global__ __launch_bounds__(256, 2) void tgemm_kernel(
    const void* __restrict__ Aa, const void* __restrict__ Ab,
    const __nv_bfloat16* __restrict__ Bhi_g, const __nv_bfloat16* __restrict__ Blo_g,
    float* __restrict__ H, int n)
{
    constexpr int KS = 40;
    constexpr int NAT = NCOLS / 16;
    __shared__ __align__(16) __nv_bfloat16 sAh[128 * KS];
    __shared__ __align__(16) __nv_bfloat16 sAl[128 * KS];
    __shared__ __align__(16) __nv_bfloat16 sBh[NCOLS * KS];
    __shared__ __align__(16) __nv_bfloat16 sBl[NCOLS * KS];

    const int tid = threadIdx.x;
    const int wid = tid >> 5, lane = tid & 31;
    const int g = lane >> 2, tg = lane & 3;
    const int wr = wid & 3;
    const int wc = wid >> 2;
    const int r0 = blockIdx.x * 128;

    float acc[2][NAT][4];
#pragma unroll
    for (int mi = 0; mi < 2; mi++)
#pragma unroll
        for (int ni = 0; ni < NAT; ni++)
#pragma unroll
            for (int q = 0; q < 4; q++) acc[mi][ni][q] = 0.0f;

    for (int s = 0; s < 4; s++) {
        for (int i = tid; i < 512; i += 256) {
            int row = i >> 2, ch = i & 3;
            int gr = r0 + row;
            uint4 vh = make_uint4(0, 0, 0, 0), vl = vh;
            if (AF32) {
                if (gr < n) {
                    const float4* X4 = (const float4*)Aa;
                    float4 f0 = X4[gr * 32 + (s * 4 + ch) * 2];
                    float4 f1 = X4[gr * 32 + (s * 4 + ch) * 2 + 1];
                    float rr[8];
                    vh.x = pack2(f0.x, f0.y, &rr[0], &rr[1]);
                    vh.y = pack2(f0.z, f0.w, &rr[2], &rr[3]);
                    vh.z = pack2(f1.x, f1.y, &rr[4], &rr[5]);
                    vh.w = pack2(f1.z, f1.w, &rr[6], &rr[7]);
                    vl.x = pack2b(rr[0], rr[1]); vl.y = pack2b(rr[2], rr[3]);
                    vl.z = pack2b(rr[4], rr[5]); vl.w = pack2b(rr[6], rr[7]);
                }
            } else {
                if (gr < n) {
                    vh = ((const uint4*)Aa)[gr * 16 + s * 4 + ch];
                    vl = ((const uint4*)Ab)[gr * 16 + s * 4 + ch];
                }
            }
            *(uint4*)&sAh[row * KS + ch * 8] = vh;
            *(uint4*)&sAl[row * KS + ch * 8] = vl;
        }
        for (int i = tid; i < NCOLS * 4; i += 256) {
            int row = i >> 2, ch = i & 3;
            *(uint4*)&sBh[row * KS + ch * 8] = ((const uint4*)Bhi_g)[row * 16 + s * 4 + ch];
            *(uint4*)&sBl[row * KS + ch * 8] = ((const uint4*)Blo_g)[row * 16 + s * 4 + ch];
        }
        __syncthreads();

#pragma unroll
        for (int pass = 0; pass < 3; pass++) {
            const __nv_bfloat16* sA = (pass == 2) ? sAl : sAh;
            const __nv_bfloat16* sB = (pass == 1) ? sBl : sBh;
#pragma unroll
            for (int kk = 0; kk < 2; kk++) {
                uint32_t a[2][4];
#pragma unroll
                for (int mi = 0; mi < 2; mi++) {
                    int rb = (wr * 32 + mi * 16 + g) * KS + kk * 16 + tg * 2;
                    a[mi][0] = *(const uint32_t*)&sA[rb];
                    a[mi][1] = *(const uint32_t*)&sA[rb + 8 * KS];
                    a[mi][2] = *(const uint32_t*)&sA[rb + 8];
                    a[mi][3] = *(const uint32_t*)&sA[rb + 8 * KS + 8];
                }
#pragma unroll
                for (int ni = 0; ni < NAT; ni++) {
                    int nb = (wc * (NCOLS / 2) + ni * 8 + g) * KS + kk * 16 + tg * 2;
                    uint32_t b0 = *(const uint32_t*)&sB[nb];
                    uint32_t b1 = *(const uint32_t*)&sB[nb + 8];
                    mma16816(acc[0][ni], a[0], b0, b1);
                    mma16816(acc[1][ni], a[1], b0, b1);
                }
            }
        }
        __syncthreads();
    }

#pragma unroll
    for (int mi = 0; mi < 2; mi++) {
        int r = r0 + wr * 32 + mi * 16 + g;
#pragma unroll
        for (int ni = 0; ni < NAT; ni++) {
            int c = wc * (NCOLS / 2) + ni * 8 + tg * 2;
            if (r < n)
                *(float2*)&H[(long long)r * NCOLS + c] = make_float2(acc[mi][ni][0], acc[mi][ni][1]);
            if (r + 8 < n)
                *(float2*)&H[(long long)(r + 8) * NCOLS + c] = make_float2(acc[mi][ni][2], acc[mi][ni][3]);
        }
    }
}

// ---------------- CSR aggregation (identical to round 15) ---------------------
__global__ __launch_bounds__(256) void agg128_kernel(const float* __restrict__ H,
                                                     const float* __restrict__ bias,
                                                     __nv_bfloat16* __restrict__ a1hi,
                                                     __nv_bfloat16* __restrict__ a1lo,
                                                     int n) {
    int warp = (blockIdx.x * blockDim.x + threadIdx.x) >> 5;
    int lane = threadIdx.x & 31;
    if (warp >= n) return;

    float4 acc0 = make_float4(0.f, 0.f, 0.f, 0.f);
    float4 acc1 = make_float4(0.f, 0.f, 0.f, 0.f);
    float4 acc2 = make_float4(0.f, 0.f, 0.f, 0.f);
    float4 acc3 = make_float4(0.f, 0.f, 0.f, 0.f);
    int beg = g_rowptr[warp], end = g_rowptr[warp + 1];
    const float4* H4 = (const float4*)H;
    int p = beg;
    for (; p + 7 < end; p += 8) {
        int2 e0 = g_csr[p];     int2 e1 = g_csr[p + 1];
        int2 e2 = g_csr[p + 2]; int2 e3 = g_csr[p + 3];
        int2 e4 = g_csr[p + 4]; int2 e5 = g_csr[p + 5];
        int2 e6 = g_csr[p + 6]; int2 e7 = g_csr[p + 7];
        float4 v0 = H4[e0.x * 32 + lane]; float4 v1 = H4[e1.x * 32 + lane];
        float4 v2 = H4[e2.x * 32 + lane]; float4 v3 = H4[e3.x * 32 + lane];
        float4 v4 = H4[e4.x * 32 + lane]; float4 v5 = H4[e5.x * 32 + lane];
        float4 v6 = H4[e6.x * 32 + lane]; float4 v7 = H4[e7.x * 32 + lane];
        float w0 = __int_as_float(e0.y), w1 = __int_as_float(e1.y);
        float w2 = __int_as_float(e2.y), w3 = __int_as_float(e3.y);
        float w4 = __int_as_float(e4.y), w5 = __int_as_float(e5.y);
        float w6 = __int_as_float(e6.y), w7 = __int_as_float(e7.y);
        acc0.x += w0 * v0.x; acc0.y += w0 * v0.y; acc0.z += w0 * v0.z; acc0.w += w0 * v0.w;
        acc1.x += w1 * v1.x; acc1.y += w1 * v1.y; acc1.z += w1 * v1.z; acc1.w += w1 * v1.w;
        acc2.x += w2 * v2.x; acc2.y += w2 * v2.y; acc2.z += w2 * v2.z; acc2.w += w2 * v2.w;
        acc3.x += w3 * v3.x; acc3.y += w3 * v3.y; acc3.z += w3 * v3.z; acc3.w += w3 * v3.w;
        acc0.x += w4 * v4.x; acc0.y += w4 * v4.y; acc0.z += w4 * v4.z; acc0.w += w4 * v4.w;
        acc1.x += w5 * v5.x; acc1.y += w5 * v5.y; acc1.z += w5 * v5.z; acc1.w += w5 * v5.w;
        acc2.x += w6 * v6.x; acc2.y += w6 * v6.y; acc2.z += w6 * v6.z; acc2.w += w6 * v6.w;
        acc3.x += w7 * v7.x; acc3.y += w7 * v7.y; acc3.z += w7 * v7.z; acc3.w += w7 * v7.w;
    }
    for (; p < end; p++) {
        int2 e0 = g_csr[p];
        float4 v0 = H4[e0.x * 32 + lane];
        float w0 = __int_as_float(e0.y);
        acc0.x += w0 * v0.x; acc0.y += w0 * v0.y; acc0.z += w0 * v0.z; acc0.w += w0 * v0.w;
    }
    acc0.x += acc1.x + acc2.x + acc3.x;
    acc0.y += acc1.y + acc2.y + acc3.y;
    acc0.z += acc1.z + acc2.z + acc3.z;
    acc0.w += acc1.w + acc2.w + acc3.w;

    float di = g_dinv[warp];
    float d2 = di * di;
    float4 hv = H4[warp * 32 + lane];
    float4 bv = ((const float4*)bias)[lane];
    float4 o;
    o.x = fmaxf(di * acc0.x + d2 * hv.x + bv.x, 0.f);
    o.y = fmaxf(di * acc0.y + d2 * hv.y + bv.y, 0.f);
    o.z = fmaxf(di * acc0.z + d2 * hv.z + bv.z, 0.f);
    o.w = fmaxf(di * acc0.w + d2 * hv.w + bv.w, 0.f);

    float rx, ry, rz, rw;
    uint2 hi, lo;
    hi.x = pack2(o.x, o.y, &rx, &ry);
    hi.y = pack2(o.z, o.w, &rz, &rw);
    lo.x = pack2b(rx, ry);
    lo.y = pack2b(rz, rw);
    ((uint2*)a1hi)[warp * 32 + lane] = hi;
    ((uint2*)a1lo)[warp * 32 + lane] = lo;
}

__global__ __launch_bounds__(256) void agg64_kernel(const float* __restrict__ H,
                                                    const float* __restrict__ bias,
                                                    float* __restrict__ out, int n) {
    int warp = (blockIdx.x * blockDim.x + threadIdx.x) >> 5;
    int lane = threadIdx.x & 31;
    if (warp >= n) return;

    float2 acc0 = make_float2(0.f, 0.f);
    float2 acc1 = make_float2(0.f, 0.f);
    float2 acc2 = make_float2(0.f, 0.f);
    float2 acc3 = make_float2(0.f, 0.f);
    int beg = g_rowptr[warp], end = g_rowptr[warp + 1];
    const float2* H2 = (const float2*)H;
    int p = beg;
    for (; p + 7 < end; p += 8) {
        int2 e0 = g_csr[p];     int2 e1 = g_csr[p + 1];
        int2 e2 = g_csr[p + 2]; int2 e3 = g_csr[p + 3];
        int2 e4 = g_csr[p + 4]; int2 e5 = g_csr[p + 5];
        int2 e6 = g_csr[p + 6]; int2 e7 = g_csr[p + 7];
        float2 v0 = H2[e0.x * 32 + lane]; float2 v1 = H2[e1.x * 32 + lane];
        float2 v2 = H2[e2.x * 32 + lane]; float2 v3 = H2[e3.x * 32 + lane];
        float2 v4 = H2[e4.x * 32 + lane]; float2 v5 = H2[e5.x * 32 + lane];
        float2 v6 = H2[e6.x * 32 + lane]; float2 v7 = H2[e7.x * 32 + lane];
        float w0 = __int_as_float(e0.y), w1 = __int_as_float(e1.y);
        float w2 = __int_as_float(e2.y), w3 = __int_as_float(e3.y);
        float w4 = __int_as_float(e4.y), w5 = __int_as_float(e5.y);
        float w6 = __int_as_float(e6.y), w7 = __int_as_float(e7.y);
        acc0.x += w0 * v0.x; acc0.y += w0 * v0.y;
        acc1.x += w1 * v1.x; acc1.y += w1 * v1.y;
        acc2.x += w2 * v2.x; acc2.y += w2 * v2.y;
        acc3.x += w3 * v3.x; acc3.y += w3 * v3.y;
        acc0.x += w4 * v4.x; acc0.y += w4 * v4.y;
        acc1.x += w5 * v5.x; acc1.y += w5 * v5.y;
        acc2.x += w6 * v6.x; acc2.y += w6 * v6.y;
        acc3.x += w7 * v7.x; acc3.y += w7 * v7.y;
    }
    for (; p < end; p++) {
        int2 e0 = g_csr[p];
        float2 v0 = H2[e0.x * 32 + lane];
        float w0 = __int_as_float(e0.y);
        acc0.x += w0 * v0.x; acc0.y += w0 * v0.y;
    }
    acc0.x += acc1.x + acc2.x + acc3.x;
    acc0.y += acc1.y + acc2.y + acc3.y;

    float di = g_dinv[warp];
    float d2 = di * di;
    float2 hv = H2[warp * 32 + lane];
    float2 bv = ((const float2*)bias)[lane];
    float2 o;
    o.x = di * acc0.x + d2 * hv.x + bv.x;
    o.y = di * acc0.y + d2 * hv.y + bv.y;
    ((float2*)out)[warp * 32 + lane] = o;
}

// ---------------- launch ------------------------------------------------------
extern "C" void kernel_launch(void* const* d_in, const int* in_sizes, int n_in,
                              void* d_out, int out_size) {
    const float* x   = (const float*)d_in[0];
    const void*  ei  = d_in[1];
    const float* W1  = (const float*)d_in[2];
    const float* b1  = (const float*)d_in[3];
    const float* W2  = (const float*)d_in[4];
    const float* b2  = (const float*)d_in[5];
    float*       out = (float*)d_out;

    const int N  = in_sizes[0] / DIN;   // 50000
    const int E  = in_sizes[1] / 2;     // 800000
    const int nb = (N + 255) / 256;     // 196
    const int eblocks = (E + 255) / 256;
    const int wblocks = (DIN * DHID + 255) / 256;  // 64

    void *p_h1, *p_h2, *p_deg, *p_a1hi, *p_a1lo;
    void *p_w1h, *p_w1l, *p_w2h, *p_w2l;
    cudaGetSymbolAddress(&p_h1, g_h1);
    cudaGetSymbolAddress(&p_h2, g_h2);
    cudaGetSymbolAddress(&p_deg, g_deg);
    cudaGetSymbolAddress(&p_a1hi, g_a1hi);
    cudaGetSymbolAddress(&p_a1lo, g_a1lo);
    cudaGetSymbolAddress(&p_w1h, g_w1thi);
    cudaGetSymbolAddress(&p_w1l, g_w1tlo);
    cudaGetSymbolAddress(&p_w2h, g_w2thi);
    cudaGetSymbolAddress(&p_w2l, g_w2tlo);

    // graph build + W split (fused launch), 3-phase scan (proven)
    cudaMemsetAsync(p_deg, 0, N * sizeof(int));
    count_w_kernel<<<eblocks + wblocks, 256>>>(ei, E, N, eblocks, W1, W2);
    scan1_kernel<<<nb, 256>>>(N);
    scan2_kernel<<<1, 256>>>(nb);
    scan3_kernel<<<nb, 256>>>(N, nb);
    fill_csr_kernel<<<eblocks, 256>>>(ei, E, N);

    const int gtiles = (N + 127) / 128;

    // layer 1: h1 = x @ W1 (mma.sync, fused fp32->hi/lo split) ; a1 = relu(conv1)
    tgemm_kernel<DHID, true><<<gtiles, 256>>>(
        x, nullptr,
        (const __nv_bfloat16*)p_w1h, (const __nv_bfloat16*)p_w1l,
        (float*)p_h1, N);
    agg128_kernel<<<(N + 7) / 8, 256>>>((const float*)p_h1, b1,
                                        (__nv_bfloat16*)p_a1hi, (__nv_bfloat16*)p_a1lo, N);

    // layer 2: h2 = a1 @ W2 (mma.sync) ; out = conv2
    tgemm_kernel<DOUT, false><<<gtiles, 256>>>(
        p_a1hi, p_a1lo,
        (const __nv_bfloat16*)p_w2h, (const __nv_bfloat16*)p_w2l,
        (float*)p_h2, N);
    agg64_kernel<<<(N + 7) / 8, 256>>>((const float*)p_h2, b2, out, N);
}